// round 12
// baseline (speedup 1.0000x reference)
#include <cuda_runtime.h>
#include <cuda_bf16.h>
#include <cstdint>

#define NN 4096
#define DD 64
#define NBLK 128   // persistent matcher blocks (<=148 SMs -> co-resident)
#define TAILN 512  // switch to in-block tail when free <= TAILN

// Scratch (device globals — no allocation allowed)
__device__ float g_cost[(size_t)NN * NN];            // 64 MB
__device__ float g_costT[(size_t)NN * NN];           // 64 MB (transpose)
__device__ float g_x2[NN];
__device__ float g_y2[NN];
__device__ unsigned long long g_rowmin[NN];
__device__ unsigned long long g_colmin[NN];
__device__ unsigned long long g_rowseg[(size_t)NN * 64];  // per-row 64-col segment min
__device__ unsigned long long g_colseg[(size_t)NN * 64];  // per-col 64-row segment min
__device__ unsigned short g_scol[NN];                // row -> cached argmin col
__device__ unsigned short g_crow[NN];                // col -> cached argmin row
__device__ unsigned int g_rowfreeG[NN / 32];
__device__ unsigned int g_colfreeG[NN / 32];
__device__ int g_matched;
__device__ int g_bar_cnt;
__device__ int g_bar_gen;

__device__ __forceinline__ unsigned long long umin64(unsigned long long a, unsigned long long b) {
    return a < b ? a : b;
}
__device__ __forceinline__ unsigned long long mkkey(float v, int idx) {
    return ((unsigned long long)__float_as_uint(v) << 32) | (unsigned)idx;
}

// Software grid barrier (all blocks co-resident; sense-reversing generation).
__device__ __forceinline__ void gridsync() {
    __threadfence();
    __syncthreads();
    if (threadIdx.x == 0) {
        int gen = atomicAdd(&g_bar_gen, 0);
        if (atomicAdd(&g_bar_cnt, 1) == NBLK - 1) {
            g_bar_cnt = 0;
            __threadfence();
            atomicExch(&g_bar_gen, gen + 1);
        } else {
            while (atomicAdd(&g_bar_gen, 0) == gen) __nanosleep(64);
        }
    }
    __syncthreads();
}

// -------------------------------------------------------------------------
// Kernel 1: squared norms + re-init of atomicMin accumulators + out prefill.
// -------------------------------------------------------------------------
__global__ void norms_kernel(const float* __restrict__ x, const float* __restrict__ y,
                             float* __restrict__ out) {
    int gt = blockIdx.x * blockDim.x + threadIdx.x;
    if (gt < NN) {
        out[gt] = (float)gt;
        g_rowmin[gt] = ~0ull;
        g_colmin[gt] = ~0ull;
    }

    int w = gt >> 5;
    int lane = gt & 31;
    if (w >= NN) return;

    float2 xv = ((const float2*)(x + w * DD))[lane];
    float p = __fadd_rn(__fmul_rn(xv.x, xv.x), __fmul_rn(xv.y, xv.y));
    #pragma unroll
    for (int o = 16; o; o >>= 1)
        p = __fadd_rn(p, __shfl_down_sync(0xFFFFFFFFu, p, o));
    if (lane == 0) g_x2[w] = p;

    float2 yv = ((const float2*)(y + w * DD))[lane];
    p = __fadd_rn(__fmul_rn(yv.x, yv.x), __fmul_rn(yv.y, yv.y));
    #pragma unroll
    for (int o = 16; o; o >>= 1)
        p = __fadd_rn(p, __shfl_down_sync(0xFFFFFFFFu, p, o));
    if (lane == 0) g_y2[w] = p;
}

// -------------------------------------------------------------------------
// Kernel 2: SGEMM-tiled cost build (validated bit-exact), fused cost+costT
// writes, per-row/col global argmins, and 64-wide SEGMENT minima.
// -------------------------------------------------------------------------
#define TSTR 68

__global__ __launch_bounds__(256)
void cost_kernel(const float* __restrict__ x, const float* __restrict__ y) {
    __shared__ __align__(16) float xsh[DD * TSTR];
    __shared__ __align__(16) float ysh[DD * TSTR];
    __shared__ unsigned long long srmin[64], scmin[64];

    int i0 = blockIdx.y * 64, j0 = blockIdx.x * 64;
    int tid = threadIdx.x;
    int tx = tid & 15, ty = tid >> 4;

    if (tid < 64) srmin[tid] = ~0ull;
    else if (tid < 128) scmin[tid - 64] = ~0ull;

    {
        int r = tid >> 2, k0 = (tid & 3) * 16;
        const float4* px = (const float4*)(x + (size_t)(i0 + r) * DD + k0);
        const float4* py = (const float4*)(y + (size_t)(j0 + r) * DD + k0);
        #pragma unroll
        for (int q = 0; q < 4; q++) {
            float4 v = px[q];
            xsh[(k0 + q * 4 + 0) * TSTR + r] = v.x;
            xsh[(k0 + q * 4 + 1) * TSTR + r] = v.y;
            xsh[(k0 + q * 4 + 2) * TSTR + r] = v.z;
            xsh[(k0 + q * 4 + 3) * TSTR + r] = v.w;
            float4 u = py[q];
            ysh[(k0 + q * 4 + 0) * TSTR + r] = u.x;
            ysh[(k0 + q * 4 + 1) * TSTR + r] = u.y;
            ysh[(k0 + q * 4 + 2) * TSTR + r] = u.z;
            ysh[(k0 + q * 4 + 3) * TSTR + r] = u.w;
        }
    }
    __syncthreads();

    float acc[4][4];
    #pragma unroll
    for (int a = 0; a < 4; a++)
        #pragma unroll
        for (int b = 0; b < 4; b++) acc[a][b] = 0.0f;

    #pragma unroll
    for (int k = 0; k < DD; k++) {
        float4 xv = *(const float4*)&xsh[k * TSTR + ty * 4];
        float4 yv = *(const float4*)&ysh[k * TSTR + tx * 4];
        float xa[4] = {xv.x, xv.y, xv.z, xv.w};
        float ya[4] = {yv.x, yv.y, yv.z, yv.w};
        #pragma unroll
        for (int a = 0; a < 4; a++)
            #pragma unroll
            for (int b = 0; b < 4; b++)
                acc[a][b] = __fmaf_rn(xa[a], ya[b], acc[a][b]);
    }

    float x2v[4], y2v[4];
    #pragma unroll
    for (int a = 0; a < 4; a++) {
        x2v[a] = g_x2[i0 + ty * 4 + a];
        y2v[a] = g_y2[j0 + tx * 4 + a];
    }
    #pragma unroll
    for (int a = 0; a < 4; a++)
        #pragma unroll
        for (int b = 0; b < 4; b++) {
            float ssum = __fadd_rn(x2v[a], y2v[b]);
            float u    = __fsub_rn(ssum, __fmul_rn(2.0f, acc[a][b]));
            float sq   = fmaxf(u, 0.0f);
            acc[a][b]  = __fsqrt_rn(sq);
        }

    #pragma unroll
    for (int a = 0; a < 4; a++) {
        unsigned long long rk = ~0ull;
        #pragma unroll
        for (int b = 0; b < 4; b++)
            rk = umin64(rk, mkkey(acc[a][b], j0 + tx * 4 + b));
        atomicMin(&srmin[ty * 4 + a], rk);
    }
    #pragma unroll
    for (int b = 0; b < 4; b++) {
        unsigned long long ck = ~0ull;
        #pragma unroll
        for (int a = 0; a < 4; a++)
            ck = umin64(ck, mkkey(acc[a][b], i0 + ty * 4 + a));
        atomicMin(&scmin[tx * 4 + b], ck);
    }

    #pragma unroll
    for (int a = 0; a < 4; a++) {
        float4 o = make_float4(acc[a][0], acc[a][1], acc[a][2], acc[a][3]);
        *(float4*)&g_cost[(size_t)(i0 + ty * 4 + a) * NN + j0 + tx * 4] = o;
    }

    __syncthreads();
    #pragma unroll
    for (int a = 0; a < 4; a++)
        #pragma unroll
        for (int b = 0; b < 4; b++)
            xsh[(tx * 4 + b) * TSTR + ty * 4 + a] = acc[a][b];
    __syncthreads();

    {
        int c = tid >> 2, k0 = (tid & 3) * 16;
        #pragma unroll
        for (int q = 0; q < 4; q++) {
            float4 v = *(const float4*)&xsh[c * TSTR + k0 + q * 4];
            *(float4*)&g_costT[(size_t)(j0 + c) * NN + i0 + k0 + q * 4] = v;
        }
    }

    if (tid < 64) {
        g_rowseg[(size_t)(i0 + tid) * 64 + blockIdx.x] = srmin[tid];
        atomicMin(&g_rowmin[i0 + tid], srmin[tid]);
    } else if (tid < 128) {
        int c = tid - 64;
        g_colseg[(size_t)(j0 + c) * 64 + blockIdx.y] = scmin[c];
        atomicMin(&g_colmin[j0 + c], scmin[c]);
    }
}

// -------------------------------------------------------------------------
// Kernel 3: init match state + barrier counters (every replay).
// -------------------------------------------------------------------------
__global__ void init_kernel() {
    int i = blockIdx.x * blockDim.x + threadIdx.x;
    if (i < NN) {
        g_scol[i] = (unsigned short)(g_rowmin[i] & 0xFFFFu);
        g_crow[i] = (unsigned short)(g_colmin[i] & 0xFFFFu);
    }
    if (i < NN / 32) { g_rowfreeG[i] = ~0u; g_colfreeG[i] = ~0u; }
    if (i == 0) { g_matched = 0; g_bar_cnt = 0; g_bar_gen = 0; }
}

// -------------------------------------------------------------------------
// Kernel 4: persistent matcher. Warp gw owns row gw + col gw. Seg caches in
// SMEM (warp-private; mirrored to global for the tail). Free bitmaps
// snapshotted to SMEM each round (stable during rescan by construction).
// Row/col rescans run concurrently in half-warps. When free <= TAILN, all
// blocks but 0 exit and block 0 finishes with cheap __syncthreads rounds.
// Exact sorted-greedy result (same invariants as validated round 9/11).
// -------------------------------------------------------------------------
__global__ __launch_bounds__(1024, 1)
void pmatch_kernel(float* __restrict__ out) {
    __shared__ __align__(16) unsigned long long wseg[32][128];  // 32 KB
    __shared__ unsigned int snap_rf[NN / 32], snap_cf[NN / 32]; // 1 KB
    __shared__ int sm_matched;

    const int tid = threadIdx.x, lane = tid & 31, w = tid >> 5;
    const int gw = blockIdx.x * 32 + w;

    // Load this warp's seg caches (warp-private -> no sync needed).
    #pragma unroll
    for (int q = 0; q < 2; q++) {
        wseg[w][q * 32 + lane]      = g_rowseg[(size_t)gw * 64 + q * 32 + lane];
        wseg[w][64 + q * 32 + lane] = g_colseg[(size_t)gw * 64 + q * 32 + lane];
    }
    int myScol = 0, myCrow = 0;
    if (lane == 0)  myScol = g_scol[gw];
    if (lane == 16) myCrow = g_crow[gw];

    while (true) {
        // ---- commit: lane 0 checks row gw (mutual edges detected row-side)
        if (lane == 0) {
            int i = gw;
            if ((__ldcg(&g_rowfreeG[i >> 5]) >> (i & 31)) & 1) {
                int j = myScol;
                if ((int)__ldcg(&g_crow[j]) == i) {
                    out[i] = (float)j;
                    atomicAnd(&g_rowfreeG[i >> 5], ~(1u << (i & 31)));
                    atomicAnd(&g_colfreeG[j >> 5], ~(1u << (j & 31)));
                    atomicAdd(&g_matched, 1);
                }
            }
        }
        gridsync();
        if (tid == 0) sm_matched = atomicAdd(&g_matched, 0);
        for (int q = tid; q < NN / 32; q += 1024) {
            snap_rf[q] = __ldcg(&g_rowfreeG[q]);
            snap_cf[q] = __ldcg(&g_colfreeG[q]);
        }
        __syncthreads();
        int m = sm_matched;
        if (m == NN) return;
        if (NN - m <= TAILN) break;

        // ---- rescan: half-warp 0 = row gw, half-warp 1 = col gw
        bool rowSide = lane < 16;
        int sl = lane & 15;
        int rowTgt = __shfl_sync(0xFFFFFFFFu, myScol, 0);
        int colTgt = __shfl_sync(0xFFFFFFFFu, myCrow, 16);
        const unsigned int* sfb = rowSide ? snap_rf : snap_cf;
        const unsigned int* ofb = rowSide ? snap_cf : snap_rf;
        int idx = gw;
        int tgt = rowSide ? rowTgt : colTgt;
        bool need = ((sfb[idx >> 5] >> (idx & 31)) & 1) &&
                    !((ofb[tgt >> 5] >> (tgt & 31)) & 1);
        unsigned long long best = ~0ull;
        if (need) {
            int segbase = rowSide ? 0 : 64;
            unsigned long long* gseg =
                (rowSide ? g_rowseg : g_colseg) + (size_t)idx * 64;
            const float* base =
                (rowSide ? g_cost : g_costT) + (size_t)idx * NN;
            #pragma unroll
            for (int it = 0; it < 4; it++) {
                int s = it * 16 + sl;
                unsigned long long k = wseg[w][segbase + s];
                if (k != ~0ull) {
                    int c = (int)(k & 0xFFFFu);
                    if (!((ofb[c >> 5] >> (c & 31)) & 1)) {
                        unsigned long long nk = ~0ull;
                        unsigned b0 = ofb[s * 2], b1 = ofb[s * 2 + 1];
                        if (b0 | b1) {
                            const float4* p = (const float4*)(base + s * 64);
                            #pragma unroll
                            for (int q = 0; q < 16; q++) {
                                unsigned mm = ((q < 8 ? b0 : b1) >> ((q & 7) * 4)) & 0xFu;
                                if (mm) {
                                    float4 v = p[q];
                                    if (mm & 1) nk = umin64(nk, mkkey(v.x, s * 64 + q * 4 + 0));
                                    if (mm & 2) nk = umin64(nk, mkkey(v.y, s * 64 + q * 4 + 1));
                                    if (mm & 4) nk = umin64(nk, mkkey(v.z, s * 64 + q * 4 + 2));
                                    if (mm & 8) nk = umin64(nk, mkkey(v.w, s * 64 + q * 4 + 3));
                                }
                            }
                        }
                        wseg[w][segbase + s] = nk;
                        gseg[s] = nk;          // keep global current for tail
                        k = nk;
                    }
                }
                best = umin64(best, k);
            }
        }
        #pragma unroll
        for (int o = 8; o; o >>= 1)
            best = umin64(best, __shfl_down_sync(0xFFFFFFFFu, best, o, 16));
        if (need && sl == 0) {
            int nc = (int)(best & 0xFFFFu);
            if (rowSide) { myScol = nc; g_scol[idx] = (unsigned short)nc; }
            else         { myCrow = nc; g_crow[idx] = (unsigned short)nc; }
        }
        gridsync();
    }

    // ================= tail: block 0 only, in-block rounds =================
    if (blockIdx.x != 0) return;
    unsigned short* tscol = (unsigned short*)&wseg[0][0];   // 8 KB alias
    unsigned short* tcrow = tscol + NN;                     // 8 KB alias
    for (int i = tid; i < NN; i += 1024) {
        tscol[i] = __ldcg(&g_scol[i]);
        tcrow[i] = __ldcg(&g_crow[i]);
    }
    __syncthreads();

    while (true) {
        // ---- commit (mutual edges disjoint -> order-independent)
        for (int i = tid; i < NN; i += 1024) {
            if ((snap_rf[i >> 5] >> (i & 31)) & 1) {
                int j = tscol[i];
                if ((int)tcrow[j] == i) {
                    out[i] = (float)j;
                    atomicAnd(&snap_rf[i >> 5], ~(1u << (i & 31)));
                    atomicAnd(&snap_cf[j >> 5], ~(1u << (j & 31)));
                    atomicAdd(&sm_matched, 1);
                }
            }
        }
        __syncthreads();
        if (sm_matched == NN) break;

        // ---- rescan: warp-per-job over 8192 jobs (rows then cols)
        for (int jj = w; jj < 2 * NN; jj += 32) {
            bool rowSide = jj < NN;
            int idx = rowSide ? jj : jj - NN;
            const unsigned int* sfb = rowSide ? snap_rf : snap_cf;
            const unsigned int* ofb = rowSide ? snap_cf : snap_rf;
            if (!((sfb[idx >> 5] >> (idx & 31)) & 1)) continue;
            int tgt = rowSide ? (int)tscol[idx] : (int)tcrow[idx];
            if ((ofb[tgt >> 5] >> (tgt & 31)) & 1) continue;

            unsigned long long* seg =
                (rowSide ? g_rowseg : g_colseg) + (size_t)idx * 64;
            const float* base =
                (rowSide ? g_cost : g_costT) + (size_t)idx * NN;
            unsigned long long best = ~0ull;
            #pragma unroll
            for (int s0 = 0; s0 < 2; s0++) {
                int s = s0 * 32 + lane;
                unsigned long long k = seg[s];
                if (k != ~0ull) {
                    int c = (int)(k & 0xFFFFu);
                    if (!((ofb[c >> 5] >> (c & 31)) & 1)) {
                        unsigned long long nk = ~0ull;
                        unsigned b0 = ofb[s * 2], b1 = ofb[s * 2 + 1];
                        if (b0 | b1) {
                            const float4* p = (const float4*)(base + s * 64);
                            #pragma unroll
                            for (int q = 0; q < 16; q++) {
                                unsigned mm = ((q < 8 ? b0 : b1) >> ((q & 7) * 4)) & 0xFu;
                                if (mm) {
                                    float4 v = p[q];
                                    if (mm & 1) nk = umin64(nk, mkkey(v.x, s * 64 + q * 4 + 0));
                                    if (mm & 2) nk = umin64(nk, mkkey(v.y, s * 64 + q * 4 + 1));
                                    if (mm & 4) nk = umin64(nk, mkkey(v.z, s * 64 + q * 4 + 2));
                                    if (mm & 8) nk = umin64(nk, mkkey(v.w, s * 64 + q * 4 + 3));
                                }
                            }
                        }
                        seg[s] = nk;
                        k = nk;
                    }
                }
                best = umin64(best, k);
            }
            #pragma unroll
            for (int o = 16; o; o >>= 1)
                best = umin64(best, __shfl_down_sync(0xFFFFFFFFu, best, o));
            if (lane == 0) {
                int nc = (int)(best & 0xFFFFu);
                if (rowSide) tscol[idx] = (unsigned short)nc;
                else         tcrow[idx] = (unsigned short)nc;
            }
        }
        __syncthreads();
    }
}

extern "C" void kernel_launch(void* const* d_in, const int* in_sizes, int n_in,
                              void* d_out, int out_size) {
    const float* x = (const float*)d_in[0];
    const float* y = (const float*)d_in[1];
    float* out = (float*)d_out;

    norms_kernel<<<512, 256>>>(x, y, out);
    cost_kernel<<<dim3(64, 64), 256>>>(x, y);
    init_kernel<<<4, 1024>>>();
    pmatch_kernel<<<NBLK, 1024>>>(out);
}

// round 15
// speedup vs baseline: 3.1128x; 3.1128x over previous
#include <cuda_runtime.h>
#include <cuda_bf16.h>
#include <cstdint>

#define NN 4096
#define DD 64
#define NBLK 128   // 128 blocks x 32 warps = 4096 warps (co-resident on 148 SMs)

// Scratch (device globals — no allocation allowed)
__device__ float g_cost[(size_t)NN * NN];            // 64 MB
__device__ float g_costT[(size_t)NN * NN];           // 64 MB (transpose)
__device__ float g_x2[NN];
__device__ float g_y2[NN];
__device__ unsigned long long g_rowmin[NN];
__device__ unsigned long long g_colmin[NN];
__device__ unsigned long long g_rowseg[(size_t)NN * 64];  // per-row 64-col segment min
__device__ unsigned long long g_colseg[(size_t)NN * 64];  // per-col 64-row segment min
__device__ unsigned short g_scol[NN];                // row -> cached argmin col (init only)
__device__ unsigned short g_crow[NN];                // col -> cached argmin row (live)
__device__ unsigned int g_rowfreeG[NN / 32];
__device__ unsigned int g_colfreeG[NN / 32];

__device__ __forceinline__ unsigned long long umin64(unsigned long long a, unsigned long long b) {
    return a < b ? a : b;
}
__device__ __forceinline__ unsigned long long mkkey(float v, int idx) {
    return ((unsigned long long)__float_as_uint(v) << 32) | (unsigned)idx;
}

// -------------------------------------------------------------------------
// Kernel 1: squared norms + re-init of atomicMin accumulators + out prefill.
// -------------------------------------------------------------------------
__global__ void norms_kernel(const float* __restrict__ x, const float* __restrict__ y,
                             float* __restrict__ out) {
    int gt = blockIdx.x * blockDim.x + threadIdx.x;
    if (gt < NN) {
        out[gt] = (float)gt;
        g_rowmin[gt] = ~0ull;
        g_colmin[gt] = ~0ull;
    }

    int w = gt >> 5;
    int lane = gt & 31;
    if (w >= NN) return;

    float2 xv = ((const float2*)(x + w * DD))[lane];
    float p = __fadd_rn(__fmul_rn(xv.x, xv.x), __fmul_rn(xv.y, xv.y));
    #pragma unroll
    for (int o = 16; o; o >>= 1)
        p = __fadd_rn(p, __shfl_down_sync(0xFFFFFFFFu, p, o));
    if (lane == 0) g_x2[w] = p;

    float2 yv = ((const float2*)(y + w * DD))[lane];
    p = __fadd_rn(__fmul_rn(yv.x, yv.x), __fmul_rn(yv.y, yv.y));
    #pragma unroll
    for (int o = 16; o; o >>= 1)
        p = __fadd_rn(p, __shfl_down_sync(0xFFFFFFFFu, p, o));
    if (lane == 0) g_y2[w] = p;
}

// -------------------------------------------------------------------------
// Kernel 2: SGEMM-tiled cost build (validated bit-exact), fused cost+costT
// writes, per-row/col global argmins, and 64-wide SEGMENT minima.
// -------------------------------------------------------------------------
#define TSTR 68

__global__ __launch_bounds__(256)
void cost_kernel(const float* __restrict__ x, const float* __restrict__ y) {
    __shared__ __align__(16) float xsh[DD * TSTR];
    __shared__ __align__(16) float ysh[DD * TSTR];
    __shared__ unsigned long long srmin[64], scmin[64];

    int i0 = blockIdx.y * 64, j0 = blockIdx.x * 64;
    int tid = threadIdx.x;
    int tx = tid & 15, ty = tid >> 4;

    if (tid < 64) srmin[tid] = ~0ull;
    else if (tid < 128) scmin[tid - 64] = ~0ull;

    {
        int r = tid >> 2, k0 = (tid & 3) * 16;
        const float4* px = (const float4*)(x + (size_t)(i0 + r) * DD + k0);
        const float4* py = (const float4*)(y + (size_t)(j0 + r) * DD + k0);
        #pragma unroll
        for (int q = 0; q < 4; q++) {
            float4 v = px[q];
            xsh[(k0 + q * 4 + 0) * TSTR + r] = v.x;
            xsh[(k0 + q * 4 + 1) * TSTR + r] = v.y;
            xsh[(k0 + q * 4 + 2) * TSTR + r] = v.z;
            xsh[(k0 + q * 4 + 3) * TSTR + r] = v.w;
            float4 u = py[q];
            ysh[(k0 + q * 4 + 0) * TSTR + r] = u.x;
            ysh[(k0 + q * 4 + 1) * TSTR + r] = u.y;
            ysh[(k0 + q * 4 + 2) * TSTR + r] = u.z;
            ysh[(k0 + q * 4 + 3) * TSTR + r] = u.w;
        }
    }
    __syncthreads();

    float acc[4][4];
    #pragma unroll
    for (int a = 0; a < 4; a++)
        #pragma unroll
        for (int b = 0; b < 4; b++) acc[a][b] = 0.0f;

    #pragma unroll
    for (int k = 0; k < DD; k++) {
        float4 xv = *(const float4*)&xsh[k * TSTR + ty * 4];
        float4 yv = *(const float4*)&ysh[k * TSTR + tx * 4];
        float xa[4] = {xv.x, xv.y, xv.z, xv.w};
        float ya[4] = {yv.x, yv.y, yv.z, yv.w};
        #pragma unroll
        for (int a = 0; a < 4; a++)
            #pragma unroll
            for (int b = 0; b < 4; b++)
                acc[a][b] = __fmaf_rn(xa[a], ya[b], acc[a][b]);
    }

    float x2v[4], y2v[4];
    #pragma unroll
    for (int a = 0; a < 4; a++) {
        x2v[a] = g_x2[i0 + ty * 4 + a];
        y2v[a] = g_y2[j0 + tx * 4 + a];
    }
    #pragma unroll
    for (int a = 0; a < 4; a++)
        #pragma unroll
        for (int b = 0; b < 4; b++) {
            float ssum = __fadd_rn(x2v[a], y2v[b]);
            float u    = __fsub_rn(ssum, __fmul_rn(2.0f, acc[a][b]));
            float sq   = fmaxf(u, 0.0f);
            acc[a][b]  = __fsqrt_rn(sq);
        }

    #pragma unroll
    for (int a = 0; a < 4; a++) {
        unsigned long long rk = ~0ull;
        #pragma unroll
        for (int b = 0; b < 4; b++)
            rk = umin64(rk, mkkey(acc[a][b], j0 + tx * 4 + b));
        atomicMin(&srmin[ty * 4 + a], rk);
    }
    #pragma unroll
    for (int b = 0; b < 4; b++) {
        unsigned long long ck = ~0ull;
        #pragma unroll
        for (int a = 0; a < 4; a++)
            ck = umin64(ck, mkkey(acc[a][b], i0 + ty * 4 + a));
        atomicMin(&scmin[tx * 4 + b], ck);
    }

    #pragma unroll
    for (int a = 0; a < 4; a++) {
        float4 o = make_float4(acc[a][0], acc[a][1], acc[a][2], acc[a][3]);
        *(float4*)&g_cost[(size_t)(i0 + ty * 4 + a) * NN + j0 + tx * 4] = o;
    }

    __syncthreads();
    #pragma unroll
    for (int a = 0; a < 4; a++)
        #pragma unroll
        for (int b = 0; b < 4; b++)
            xsh[(tx * 4 + b) * TSTR + ty * 4 + a] = acc[a][b];
    __syncthreads();

    {
        int c = tid >> 2, k0 = (tid & 3) * 16;
        #pragma unroll
        for (int q = 0; q < 4; q++) {
            float4 v = *(const float4*)&xsh[c * TSTR + k0 + q * 4];
            *(float4*)&g_costT[(size_t)(j0 + c) * NN + i0 + k0 + q * 4] = v;
        }
    }

    if (tid < 64) {
        g_rowseg[(size_t)(i0 + tid) * 64 + blockIdx.x] = srmin[tid];
        atomicMin(&g_rowmin[i0 + tid], srmin[tid]);
    } else if (tid < 128) {
        int c = tid - 64;
        g_colseg[(size_t)(j0 + c) * 64 + blockIdx.y] = scmin[c];
        atomicMin(&g_colmin[j0 + c], scmin[c]);
    }
}

// -------------------------------------------------------------------------
// Kernel 3: init match state (every replay).
// -------------------------------------------------------------------------
__global__ void init_kernel() {
    int i = blockIdx.x * blockDim.x + threadIdx.x;
    if (i < NN) {
        g_scol[i] = (unsigned short)(g_rowmin[i] & 0xFFFFu);
        g_crow[i] = (unsigned short)(g_colmin[i] & 0xFFFFu);
    }
    if (i < NN / 32) { g_rowfreeG[i] = ~0u; g_colfreeG[i] = ~0u; }
}

// -------------------------------------------------------------------------
// Kernel 4: ASYNC matcher — no barriers. Warp gw owns row gw and col gw.
// Loop: (row) if pointer dead -> rescan; if mutual -> claim col bit
// (atomicAnd linearization) and commit. (col) if own col taken -> done;
// if pointer dead -> rescan + publish crow. Exit when both done.
// Exactness: pointers are superset-argmins; a free superset-argmin is the
// true argmin (free sets shrink monotonically); crow[j] only changes after
// j is matched, closing the check->claim race. Progress: the global min
// free edge becomes mutual after <=1 rescan per side, so commits always
// proceed; no livelock. All cross-warp state via volatile/atomics (L2).
// -------------------------------------------------------------------------
__global__ __launch_bounds__(1024, 1)
void pmatch_kernel(float* __restrict__ out) {
    __shared__ __align__(16) unsigned long long wseg[32][128];  // 32 KB, warp-private

    const int lane = threadIdx.x & 31, w = threadIdx.x >> 5;
    const int gw = blockIdx.x * 32 + w;

    volatile unsigned int* vcf = (volatile unsigned int*)g_colfreeG;
    volatile unsigned int* vrf = (volatile unsigned int*)g_rowfreeG;
    volatile unsigned short* vcrow = (volatile unsigned short*)g_crow;

    #pragma unroll
    for (int q = 0; q < 2; q++) {
        wseg[w][q * 32 + lane]      = g_rowseg[(size_t)gw * 64 + q * 32 + lane];
        wseg[w][64 + q * 32 + lane] = g_colseg[(size_t)gw * 64 + q * 32 + lane];
    }
    int scolReg = g_scol[gw];
    int crowReg = g_crow[gw];
    bool rowDone = false, colDone = false;

    while (true) {
        bool didWork = false;

        // ---------------- row side (we exclusively own row gw) -----------
        if (!rowDone) {
            int j = scolReg;
            unsigned cw = vcf[j >> 5];
            if (!((cw >> (j & 31)) & 1)) {
                // pointer dead -> rescan row over seg hierarchy
                unsigned long long best = ~0ull;
                const float* base = g_cost + (size_t)gw * NN;
                #pragma unroll
                for (int s0 = 0; s0 < 2; s0++) {
                    int s = s0 * 32 + lane;
                    unsigned long long k = wseg[w][s];
                    if (k != ~0ull) {
                        int c = (int)(k & 0xFFFFu);
                        if (!((vcf[c >> 5] >> (c & 31)) & 1)) {
                            unsigned long long nk = ~0ull;
                            unsigned b0 = vcf[s * 2], b1 = vcf[s * 2 + 1];
                            if (b0 | b1) {
                                const float4* p = (const float4*)(base + s * 64);
                                #pragma unroll
                                for (int q = 0; q < 16; q++) {
                                    unsigned mm = ((q < 8 ? b0 : b1) >> ((q & 7) * 4)) & 0xFu;
                                    if (mm) {
                                        float4 v = p[q];
                                        if (mm & 1) nk = umin64(nk, mkkey(v.x, s * 64 + q * 4 + 0));
                                        if (mm & 2) nk = umin64(nk, mkkey(v.y, s * 64 + q * 4 + 1));
                                        if (mm & 4) nk = umin64(nk, mkkey(v.z, s * 64 + q * 4 + 2));
                                        if (mm & 8) nk = umin64(nk, mkkey(v.w, s * 64 + q * 4 + 3));
                                    }
                                }
                            }
                            wseg[w][s] = nk;
                            k = nk;
                        }
                    }
                    best = umin64(best, k);
                }
                #pragma unroll
                for (int o = 16; o; o >>= 1)
                    best = umin64(best, __shfl_down_sync(0xFFFFFFFFu, best, o));
                scolReg = (int)(__shfl_sync(0xFFFFFFFFu, best, 0) & 0xFFFFu);
                didWork = true;
            } else {
                int cr = (int)vcrow[j];
                if (cr == gw) {
                    unsigned old = 0;
                    if (lane == 0)
                        old = atomicAnd(&g_colfreeG[j >> 5], ~(1u << (j & 31)));
                    old = __shfl_sync(0xFFFFFFFFu, old, 0);
                    if ((old >> (j & 31)) & 1) {
                        if (lane == 0) {
                            out[gw] = (float)j;
                            atomicAnd(&g_rowfreeG[gw >> 5], ~(1u << (gw & 31)));
                        }
                        rowDone = true;
                        didWork = true;
                    }
                    // claim failed -> col died; next iteration rescans
                }
            }
        }

        // ---------------- col side (we maintain crow[gw]) ----------------
        if (!colDone) {
            unsigned cw = vcf[gw >> 5];
            if (!((cw >> (gw & 31)) & 1)) {
                colDone = true;
            } else {
                int r2 = crowReg;
                unsigned rw = vrf[r2 >> 5];
                if (!((rw >> (r2 & 31)) & 1)) {
                    unsigned long long best = ~0ull;
                    const float* base = g_costT + (size_t)gw * NN;
                    #pragma unroll
                    for (int s0 = 0; s0 < 2; s0++) {
                        int s = s0 * 32 + lane;
                        unsigned long long k = wseg[w][64 + s];
                        if (k != ~0ull) {
                            int c = (int)(k & 0xFFFFu);
                            if (!((vrf[c >> 5] >> (c & 31)) & 1)) {
                                unsigned long long nk = ~0ull;
                                unsigned b0 = vrf[s * 2], b1 = vrf[s * 2 + 1];
                                if (b0 | b1) {
                                    const float4* p = (const float4*)(base + s * 64);
                                    #pragma unroll
                                    for (int q = 0; q < 16; q++) {
                                        unsigned mm = ((q < 8 ? b0 : b1) >> ((q & 7) * 4)) & 0xFu;
                                        if (mm) {
                                            float4 v = p[q];
                                            if (mm & 1) nk = umin64(nk, mkkey(v.x, s * 64 + q * 4 + 0));
                                            if (mm & 2) nk = umin64(nk, mkkey(v.y, s * 64 + q * 4 + 1));
                                            if (mm & 4) nk = umin64(nk, mkkey(v.z, s * 64 + q * 4 + 2));
                                            if (mm & 8) nk = umin64(nk, mkkey(v.w, s * 64 + q * 4 + 3));
                                        }
                                    }
                                }
                                wseg[w][64 + s] = nk;
                                k = nk;
                            }
                        }
                        best = umin64(best, k);
                    }
                    #pragma unroll
                    for (int o = 16; o; o >>= 1)
                        best = umin64(best, __shfl_down_sync(0xFFFFFFFFu, best, o));
                    crowReg = (int)(__shfl_sync(0xFFFFFFFFu, best, 0) & 0xFFFFu);
                    if (lane == 0) {
                        vcrow[gw] = (unsigned short)crowReg;   // volatile -> L2 visible
                        __threadfence();
                    }
                    didWork = true;
                }
            }
        }

        if (rowDone && colDone) break;
        if (!didWork) __nanosleep(128);
    }
}

extern "C" void kernel_launch(void* const* d_in, const int* in_sizes, int n_in,
                              void* d_out, int out_size) {
    const float* x = (const float*)d_in[0];
    const float* y = (const float*)d_in[1];
    float* out = (float*)d_out;

    norms_kernel<<<512, 256>>>(x, y, out);
    cost_kernel<<<dim3(64, 64), 256>>>(x, y);
    init_kernel<<<4, 1024>>>();
    pmatch_kernel<<<NBLK, 1024>>>(out);
}